// round 9
// baseline (speedup 1.0000x reference)
#include <cuda_runtime.h>
#include <cuda_bf16.h>
#include <cstdint>

#define RES    56
#define DIMS   192
#define HEADS  6
#define NTOK   49
#define NPIX   200704
#define QKVC   576
#define ASTRIDE 200          // A smem row stride in bf16 elems (400B -> ldmatrix conflict-free)

// static device scratch (no runtime allocation allowed)
__device__ float g_qkv[(size_t)NPIX * QKVC];   // 462 MB
__device__ float g_att[(size_t)NPIX * DIMS];   // 154 MB
__device__ uint4 g_wfrag[96 * 12 * 32];        // B fragments: 96 ntiles x 12 ksteps x 32 lanes
__device__ float g_bias[768];                  // bq|bk|bv (576) then bo (192)

__device__ __forceinline__ uint32_t smem_u32(const void* p){
    uint32_t a;
    asm("{ .reg .u64 t; cvta.to.shared.u64 t, %1; cvt.u32.u64 %0, t; }" : "=r"(a) : "l"(p));
    return a;
}
__device__ __forceinline__ uint32_t pack2(__nv_bfloat16 a, __nv_bfloat16 b){
    return (uint32_t)__bfloat16_as_ushort(a) | ((uint32_t)__bfloat16_as_ushort(b) << 16);
}
__device__ __forceinline__ void ldmx4(uint32_t* r, uint32_t addr){
    asm volatile("ldmatrix.sync.aligned.m8n8.x4.shared.b16 {%0,%1,%2,%3}, [%4];"
        : "=r"(r[0]), "=r"(r[1]), "=r"(r[2]), "=r"(r[3]) : "r"(addr));
}
__device__ __forceinline__ void mma16816(float* c, const uint32_t* a, uint32_t b0, uint32_t b1){
    asm volatile("mma.sync.aligned.m16n8k16.row.col.f32.bf16.bf16.f32 "
        "{%0,%1,%2,%3}, {%4,%5,%6,%7}, {%8,%9}, {%0,%1,%2,%3};"
        : "+f"(c[0]), "+f"(c[1]), "+f"(c[2]), "+f"(c[3])
        : "r"(a[0]), "r"(a[1]), "r"(a[2]), "r"(a[3]), "r"(b0), "r"(b1));
}

// ---- packed f32x2 helpers (Blackwell FFMA2; PTX-only pattern) ----
__device__ __forceinline__ void lds_v2u64(uint64_t& a, uint64_t& b, uint32_t addr){
    asm volatile("ld.shared.v2.u64 {%0,%1}, [%2];" : "=l"(a), "=l"(b) : "r"(addr));
}
__device__ __forceinline__ uint64_t fma_x2(uint64_t a, uint64_t b, uint64_t c){
    uint64_t d; asm("fma.rn.f32x2 %0, %1, %2, %3;" : "=l"(d) : "l"(a), "l"(b), "l"(c)); return d;
}
__device__ __forceinline__ uint64_t mul_x2(uint64_t a, uint64_t b){
    uint64_t d; asm("mul.rn.f32x2 %0, %1, %2;" : "=l"(d) : "l"(a), "l"(b)); return d;
}
__device__ __forceinline__ uint64_t add_x2(uint64_t a, uint64_t b){
    uint64_t d; asm("add.rn.f32x2 %0, %1, %2;" : "=l"(d) : "l"(a), "l"(b)); return d;
}
__device__ __forceinline__ uint64_t pack_x2(float lo, float hi){
    uint64_t d; asm("mov.b64 %0, {%1,%2};" : "=l"(d) : "f"(lo), "f"(hi)); return d;
}
__device__ __forceinline__ void unpack_x2(float& lo, float& hi, uint64_t v){
    asm("mov.b64 {%0,%1}, %2;" : "=f"(lo), "=f"(hi) : "l"(v));
}

// =====================================================================
// One-time weight prep (unchanged)
// =====================================================================
__global__ void wprep_kernel(const float* __restrict__ wq, const float* __restrict__ wk,
                             const float* __restrict__ wv, const float* __restrict__ wo,
                             const float* __restrict__ bq, const float* __restrict__ bk,
                             const float* __restrict__ bv, const float* __restrict__ bo)
{
    int t = blockIdx.x * 256 + threadIdx.x;
    if (t < 768){
        float b;
        if      (t < 192) b = bq[t];
        else if (t < 384) b = bk[t - 192];
        else if (t < 576) b = bv[t - 384];
        else              b = bo[t - 576];
        g_bias[t] = b;
    }
    if (t >= 96*12*32) return;
    int ntile = t / 384;
    int rem   = t - ntile*384;
    int ks    = rem >> 5;
    int lane  = rem & 31;
    int nl    = lane >> 2;
    int k0    = ks*16 + (lane & 3)*2;

    const float* W; int col;
    if (ntile < 72){
        int ng = ntile*8 + nl;
        int mat = ng / 192; col = ng - mat*192;
        W = (mat == 0) ? wq : ((mat == 1) ? wk : wv);
    } else {
        col = (ntile - 72)*8 + nl;
        W = wo;
    }
    float e0 = W[(k0+0)*192 + col], e1 = W[(k0+1)*192 + col];
    float e2 = W[(k0+8)*192 + col], e3 = W[(k0+9)*192 + col];
    __nv_bfloat16 h0 = __float2bfloat16(e0), h1 = __float2bfloat16(e1),
                  h2 = __float2bfloat16(e2), h3 = __float2bfloat16(e3);
    __nv_bfloat16 l0 = __float2bfloat16(e0 - __bfloat162float(h0)),
                  l1 = __float2bfloat16(e1 - __bfloat162float(h1)),
                  l2 = __float2bfloat16(e2 - __bfloat162float(h2)),
                  l3 = __float2bfloat16(e3 - __bfloat162float(h3));
    uint4 v;
    v.x = pack2(h0, h1);
    v.y = pack2(h2, h3);
    v.z = pack2(l0, l1);
    v.w = pack2(l2, l3);
    g_wfrag[t] = v;
}

// =====================================================================
// GEMM (unchanged): 3-term bf16 MMA, fp32 accum
// =====================================================================
#define GEMM_SMEM (2 * 128 * ASTRIDE * 2)

__global__ __launch_bounds__(256, 2)
void mma_gemm(const float* __restrict__ A, float* __restrict__ Out,
              int outStride, int ntStart, int ntCount, int biasOff)
{
    extern __shared__ char smc[];
    __nv_bfloat16* sH = (__nv_bfloat16*)smc;
    __nv_bfloat16* sL = sH + 128 * ASTRIDE;

    const int tid = threadIdx.x, wid = tid >> 5, lane = tid & 31;
    const float* Ab = A + (size_t)blockIdx.x * 128 * 192;

    for (int f = tid; f < 6144; f += 256){
        int r  = f / 48;
        int kk = (f - r*48) * 4;
        float4 v = *(const float4*)(Ab + r*192 + kk);
        __nv_bfloat16 h0 = __float2bfloat16(v.x), h1 = __float2bfloat16(v.y),
                      h2 = __float2bfloat16(v.z), h3 = __float2bfloat16(v.w);
        __nv_bfloat16 l0 = __float2bfloat16(v.x - __bfloat162float(h0)),
                      l1 = __float2bfloat16(v.y - __bfloat162float(h1)),
                      l2 = __float2bfloat16(v.z - __bfloat162float(h2)),
                      l3 = __float2bfloat16(v.w - __bfloat162float(h3));
        uint2 hv, lv;
        hv.x = pack2(h0, h1); hv.y = pack2(h2, h3);
        lv.x = pack2(l0, l1); lv.y = pack2(l2, l3);
        *(uint2*)(sH + r*ASTRIDE + kk) = hv;
        *(uint2*)(sL + r*ASTRIDE + kk) = lv;
    }
    __syncthreads();

    uint32_t ah[12][4], al[12][4];
    {
        int row  = wid*16 + (lane & 15);
        int coff = (lane >> 4) * 8;
        #pragma unroll
        for (int ks = 0; ks < 12; ++ks){
            uint32_t aH = smem_u32(sH + row*ASTRIDE + ks*16 + coff);
            uint32_t aL = smem_u32(sL + row*ASTRIDE + ks*16 + coff);
            ldmx4(ah[ks], aH);
            ldmx4(al[ks], aL);
        }
    }

    const int rowg = blockIdx.x*128 + wid*16 + (lane >> 2);
    const int cloc = (lane & 3) * 2;

    for (int nt = 0; nt < ntCount; ++nt){
        const uint4* bp = g_wfrag + (size_t)(ntStart + nt)*384 + lane;
        float c0[4] = {0,0,0,0}, c1[4] = {0,0,0,0}, c2[4] = {0,0,0,0};
        #pragma unroll
        for (int ks = 0; ks < 12; ++ks){
            uint4 bv = bp[ks*32];
            mma16816(c0, ah[ks], bv.x, bv.y);
            mma16816(c1, al[ks], bv.x, bv.y);
            mma16816(c2, ah[ks], bv.z, bv.w);
        }
        int cb = nt*8 + cloc;
        float b0 = g_bias[biasOff + cb], b1 = g_bias[biasOff + cb + 1];
        float2 o0, o1;
        o0.x = c0[0] + c1[0] + c2[0] + b0;
        o0.y = c0[1] + c1[1] + c2[1] + b1;
        o1.x = c0[2] + c1[2] + c2[2] + b0;
        o1.y = c0[3] + c1[3] + c2[3] + b1;
        *(float2*)(Out + (size_t)rowg     * outStride + cb) = o0;
        *(float2*)(Out + (size_t)(rowg+8) * outStride + cb) = o1;
    }
}

// =====================================================================
// Attention: one CTA per (window, head). 64 threads, f32x2 inner loops.
// Thread i (<49) owns query row i.
// =====================================================================
#define SCP 51

__global__ __launch_bounds__(64, 9)
void attn_kernel(const float* __restrict__ table,
                 const float* __restrict__ qkv,
                 float* __restrict__ att)
{
    __shared__ float sK[NTOK*32];
    __shared__ float sV[NTOK*32];
    __shared__ float sSC[NTOK*SCP];
    __shared__ float sB[169];
    __shared__ int   PIX[NTOK];
    __shared__ int   CNT[NTOK];

    const int tid = threadIdx.x;
    const int win = blockIdx.x;
    const int h   = blockIdx.y;
    const int b   = win >> 6, wi = win & 63;
    const int wh  = wi >> 3,  ww = wi & 7;
    const int mh  = b >> 3,   mw = b & 7;   // mask window = BATCH index (reference quirk)

    if (tid < NTOK){
        int th = tid / 7, tw = tid - th*7;
        int hh = wh*7 + th + 3; if (hh >= RES) hh -= RES;
        int wc = ww*7 + tw + 3; if (wc >= RES) wc -= RES;
        PIX[tid] = (b*RES + hh)*RES + wc;
        int mhs = mh*7 + th, mws = mw*7 + tw;
        int rh = (mhs < 49) ? 0 : ((mhs < 53) ? 1 : 2);
        int rw = (mws < 49) ? 0 : ((mws < 53) ? 1 : 2);
        CNT[tid] = rh*3 + rw;
    }
    for (int t = tid; t < 169; t += 64) sB[t] = __ldg(table + t*HEADS + h);
    __syncthreads();

    // gather K, V for this head (49 x 32 floats each)
    for (int f = tid; f < NTOK*8; f += 64){
        int t  = f >> 3;
        int c4 = (f & 7) * 4;
        const float* base = qkv + (size_t)PIX[t]*QKVC + h*32;
        *(float4*)(sK + t*32 + c4) = *(const float4*)(base + 192 + c4);
        *(float4*)(sV + t*32 + c4) = *(const float4*)(base + 384 + c4);
    }
    __syncthreads();

    if (tid < NTOK){
        const int i  = tid;
        const int ih = i / 7, iw = i - ih*7;
        const int ci = CNT[i];
        const float scale = 0.17677669529663687f;

        // Q row (32 floats) -> 16 packed f32x2 regs
        uint64_t q2[16];
        {
            const float4* qp = (const float4*)(qkv + (size_t)PIX[i]*QKVC + h*32);
            #pragma unroll
            for (int d = 0; d < 8; ++d){
                float4 v = qp[d];
                q2[d*2+0] = pack_x2(v.x, v.y);
                q2[d*2+1] = pack_x2(v.z, v.w);
            }
        }

        // ---- scores: packed dot + bias + mask ----
        float* srow = sSC + i*SCP;
        const uint32_t sKb = smem_u32(sK);
        int jh = 0, jw = 0;
        for (int j = 0; j < NTOK; ++j){
            uint32_t ka = sKb + j*128;
            uint64_t k2[16];
            #pragma unroll
            for (int d = 0; d < 8; ++d) lds_v2u64(k2[d*2], k2[d*2+1], ka + d*16);
            uint64_t a0 = mul_x2(q2[0], k2[0]);
            uint64_t a1 = mul_x2(q2[1], k2[1]);
            uint64_t a2 = mul_x2(q2[2], k2[2]);
            uint64_t a3 = mul_x2(q2[3], k2[3]);
            #pragma unroll
            for (int d = 4; d < 16; d += 4){
                a0 = fma_x2(q2[d+0], k2[d+0], a0);
                a1 = fma_x2(q2[d+1], k2[d+1], a1);
                a2 = fma_x2(q2[d+2], k2[d+2], a2);
                a3 = fma_x2(q2[d+3], k2[d+3], a3);
            }
            uint64_t s01 = add_x2(a0, a1);
            uint64_t s23 = add_x2(a2, a3);
            uint64_t s   = add_x2(s01, s23);
            float lo, hi; unpack_x2(lo, hi, s);
            float bias = sB[(ih - jh + 6)*13 + (iw - jw + 6)];
            float mv = (ci == CNT[j]) ? 0.f : -1000.f;
            srow[j] = fmaf(lo + hi, scale, bias + mv);
            if (++jw == 7){ jw = 0; ++jh; }
        }

        // ---- softmax ----
        float mx = -1e30f;
        #pragma unroll 7
        for (int j = 0; j < NTOK; ++j) mx = fmaxf(mx, srow[j]);
        float sum = 0.f;
        #pragma unroll 7
        for (int j = 0; j < NTOK; ++j){ float e = __expf(srow[j] - mx); srow[j] = e; sum += e; }
        float inv = __fdividef(1.f, sum);

        // ---- O = P @ V, packed accumulators ----
        uint64_t acc[16];
        const uint32_t sVb = smem_u32(sV);
        {
            // j = 0 initializes
            float p0 = srow[0];
            uint64_t pd = pack_x2(p0, p0);
            uint64_t v2[16];
            #pragma unroll
            for (int d = 0; d < 8; ++d) lds_v2u64(v2[d*2], v2[d*2+1], sVb + d*16);
            #pragma unroll
            for (int d = 0; d < 16; ++d) acc[d] = mul_x2(pd, v2[d]);
        }
        for (int j = 1; j < NTOK; ++j){
            float p = srow[j];
            uint64_t pd = pack_x2(p, p);
            uint32_t va = sVb + j*128;
            uint64_t v2[16];
            #pragma unroll
            for (int d = 0; d < 8; ++d) lds_v2u64(v2[d*2], v2[d*2+1], va + d*16);
            #pragma unroll
            for (int d = 0; d < 16; ++d) acc[d] = fma_x2(pd, v2[d], acc[d]);
        }
        uint64_t inv2 = pack_x2(inv, inv);
        float* ob = att + (size_t)PIX[i]*DIMS + h*32;
        #pragma unroll
        for (int d = 0; d < 4; ++d){
            float4 o;
            uint64_t r0 = mul_x2(acc[d*4+0], inv2);
            uint64_t r1 = mul_x2(acc[d*4+1], inv2);
            unpack_x2(o.x, o.y, r0);
            unpack_x2(o.z, o.w, r1);
            *(float4*)(ob + d*8) = o;
            float4 o2;
            uint64_t r2 = mul_x2(acc[d*4+2], inv2);
            uint64_t r3 = mul_x2(acc[d*4+3], inv2);
            unpack_x2(o2.x, o2.y, r2);
            unpack_x2(o2.z, o2.w, r3);
            *(float4*)(ob + d*8 + 4) = o2;
        }
    }
}

// =====================================================================
extern "C" void kernel_launch(void* const* d_in, const int* in_sizes, int n_in,
                              void* d_out, int out_size)
{
    const float* x     = (const float*)d_in[0];
    const float* table = (const float*)d_in[1];
    const float* wq    = (const float*)d_in[2];
    const float* bq    = (const float*)d_in[3];
    const float* wk    = (const float*)d_in[4];
    const float* bk    = (const float*)d_in[5];
    const float* wv    = (const float*)d_in[6];
    const float* bv    = (const float*)d_in[7];
    const float* wo    = (const float*)d_in[8];
    const float* bo    = (const float*)d_in[9];
    float* out = (float*)d_out;

    void* qkvp = nullptr; void* attp = nullptr;
    cudaGetSymbolAddress(&qkvp, g_qkv);
    cudaGetSymbolAddress(&attp, g_att);

    cudaFuncSetAttribute(mma_gemm, cudaFuncAttributeMaxDynamicSharedMemorySize, GEMM_SMEM);

    // 0) weight fragment prep
    wprep_kernel<<<144, 256>>>(wq, wk, wv, wo, bq, bk, bv, bo);
    // 1) QKV projection
    mma_gemm<<<NPIX/128, 256, GEMM_SMEM>>>(x, (float*)qkvp, QKVC, 0, 72, 0);
    // 2) windowed attention, one CTA per (window, head)
    dim3 ag(4096, 6);
    attn_kernel<<<ag, 64>>>(table, (const float*)qkvp, (float*)attp);
    // 3) output projection
    mma_gemm<<<NPIX/128, 256, GEMM_SMEM>>>((const float*)attp, out, DIMS, 72, 24, 576);
}

// round 10
// speedup vs baseline: 1.0254x; 1.0254x over previous
#include <cuda_runtime.h>
#include <cuda_bf16.h>
#include <cstdint>

#define RES    56
#define DIMS   192
#define HEADS  6
#define NTOK   49
#define NPIX   200704
#define QKVC   576
#define ASTRIDE 200          // A smem row stride in bf16 elems (400B -> ldmatrix conflict-free)

// static device scratch (no runtime allocation allowed)
__device__ float g_qkv[(size_t)NPIX * QKVC];   // 462 MB
__device__ float g_att[(size_t)NPIX * DIMS];   // 154 MB
__device__ uint4 g_wfrag[96 * 12 * 32];        // B fragments: 96 ntiles x 12 ksteps x 32 lanes
__device__ float g_bias[768];                  // bq|bk|bv (576) then bo (192)

__device__ __forceinline__ uint32_t smem_u32(const void* p){
    uint32_t a;
    asm("{ .reg .u64 t; cvta.to.shared.u64 t, %1; cvt.u32.u64 %0, t; }" : "=r"(a) : "l"(p));
    return a;
}
__device__ __forceinline__ uint32_t pack2(__nv_bfloat16 a, __nv_bfloat16 b){
    return (uint32_t)__bfloat16_as_ushort(a) | ((uint32_t)__bfloat16_as_ushort(b) << 16);
}
__device__ __forceinline__ void ldmx4(uint32_t* r, uint32_t addr){
    asm volatile("ldmatrix.sync.aligned.m8n8.x4.shared.b16 {%0,%1,%2,%3}, [%4];"
        : "=r"(r[0]), "=r"(r[1]), "=r"(r[2]), "=r"(r[3]) : "r"(addr));
}
__device__ __forceinline__ void mma16816(float* c, const uint32_t* a, uint32_t b0, uint32_t b1){
    asm volatile("mma.sync.aligned.m16n8k16.row.col.f32.bf16.bf16.f32 "
        "{%0,%1,%2,%3}, {%4,%5,%6,%7}, {%8,%9}, {%0,%1,%2,%3};"
        : "+f"(c[0]), "+f"(c[1]), "+f"(c[2]), "+f"(c[3])
        : "r"(a[0]), "r"(a[1]), "r"(a[2]), "r"(a[3]), "r"(b0), "r"(b1));
}

// ---- packed f32x2 helpers (Blackwell FFMA2; PTX-only pattern) ----
__device__ __forceinline__ void lds_v2u64(uint64_t& a, uint64_t& b, uint32_t addr){
    asm volatile("ld.shared.v2.u64 {%0,%1}, [%2];" : "=l"(a), "=l"(b) : "r"(addr));
}
__device__ __forceinline__ uint64_t fma_x2(uint64_t a, uint64_t b, uint64_t c){
    uint64_t d; asm("fma.rn.f32x2 %0, %1, %2, %3;" : "=l"(d) : "l"(a), "l"(b), "l"(c)); return d;
}
__device__ __forceinline__ uint64_t mul_x2(uint64_t a, uint64_t b){
    uint64_t d; asm("mul.rn.f32x2 %0, %1, %2;" : "=l"(d) : "l"(a), "l"(b)); return d;
}
__device__ __forceinline__ uint64_t add_x2(uint64_t a, uint64_t b){
    uint64_t d; asm("add.rn.f32x2 %0, %1, %2;" : "=l"(d) : "l"(a), "l"(b)); return d;
}
__device__ __forceinline__ uint64_t pack_x2(float lo, float hi){
    uint64_t d; asm("mov.b64 %0, {%1,%2};" : "=l"(d) : "f"(lo), "f"(hi)); return d;
}
__device__ __forceinline__ void unpack_x2(float& lo, float& hi, uint64_t v){
    asm("mov.b64 {%0,%1}, %2;" : "=f"(lo), "=f"(hi) : "l"(v));
}

// =====================================================================
// One-time weight prep (unchanged)
// =====================================================================
__global__ void wprep_kernel(const float* __restrict__ wq, const float* __restrict__ wk,
                             const float* __restrict__ wv, const float* __restrict__ wo,
                             const float* __restrict__ bq, const float* __restrict__ bk,
                             const float* __restrict__ bv, const float* __restrict__ bo)
{
    int t = blockIdx.x * 256 + threadIdx.x;
    if (t < 768){
        float b;
        if      (t < 192) b = bq[t];
        else if (t < 384) b = bk[t - 192];
        else if (t < 576) b = bv[t - 384];
        else              b = bo[t - 576];
        g_bias[t] = b;
    }
    if (t >= 96*12*32) return;
    int ntile = t / 384;
    int rem   = t - ntile*384;
    int ks    = rem >> 5;
    int lane  = rem & 31;
    int nl    = lane >> 2;
    int k0    = ks*16 + (lane & 3)*2;

    const float* W; int col;
    if (ntile < 72){
        int ng = ntile*8 + nl;
        int mat = ng / 192; col = ng - mat*192;
        W = (mat == 0) ? wq : ((mat == 1) ? wk : wv);
    } else {
        col = (ntile - 72)*8 + nl;
        W = wo;
    }
    float e0 = W[(k0+0)*192 + col], e1 = W[(k0+1)*192 + col];
    float e2 = W[(k0+8)*192 + col], e3 = W[(k0+9)*192 + col];
    __nv_bfloat16 h0 = __float2bfloat16(e0), h1 = __float2bfloat16(e1),
                  h2 = __float2bfloat16(e2), h3 = __float2bfloat16(e3);
    __nv_bfloat16 l0 = __float2bfloat16(e0 - __bfloat162float(h0)),
                  l1 = __float2bfloat16(e1 - __bfloat162float(h1)),
                  l2 = __float2bfloat16(e2 - __bfloat162float(h2)),
                  l3 = __float2bfloat16(e3 - __bfloat162float(h3));
    uint4 v;
    v.x = pack2(h0, h1);
    v.y = pack2(h2, h3);
    v.z = pack2(l0, l1);
    v.w = pack2(l2, l3);
    g_wfrag[t] = v;
}

// =====================================================================
// GEMM (unchanged): 3-term bf16 MMA, fp32 accum
// =====================================================================
#define GEMM_SMEM (2 * 128 * ASTRIDE * 2)

__global__ __launch_bounds__(256, 2)
void mma_gemm(const float* __restrict__ A, float* __restrict__ Out,
              int outStride, int ntStart, int ntCount, int biasOff)
{
    extern __shared__ char smc[];
    __nv_bfloat16* sH = (__nv_bfloat16*)smc;
    __nv_bfloat16* sL = sH + 128 * ASTRIDE;

    const int tid = threadIdx.x, wid = tid >> 5, lane = tid & 31;
    const float* Ab = A + (size_t)blockIdx.x * 128 * 192;

    for (int f = tid; f < 6144; f += 256){
        int r  = f / 48;
        int kk = (f - r*48) * 4;
        float4 v = *(const float4*)(Ab + r*192 + kk);
        __nv_bfloat16 h0 = __float2bfloat16(v.x), h1 = __float2bfloat16(v.y),
                      h2 = __float2bfloat16(v.z), h3 = __float2bfloat16(v.w);
        __nv_bfloat16 l0 = __float2bfloat16(v.x - __bfloat162float(h0)),
                      l1 = __float2bfloat16(v.y - __bfloat162float(h1)),
                      l2 = __float2bfloat16(v.z - __bfloat162float(h2)),
                      l3 = __float2bfloat16(v.w - __bfloat162float(h3));
        uint2 hv, lv;
        hv.x = pack2(h0, h1); hv.y = pack2(h2, h3);
        lv.x = pack2(l0, l1); lv.y = pack2(l2, l3);
        *(uint2*)(sH + r*ASTRIDE + kk) = hv;
        *(uint2*)(sL + r*ASTRIDE + kk) = lv;
    }
    __syncthreads();

    uint32_t ah[12][4], al[12][4];
    {
        int row  = wid*16 + (lane & 15);
        int coff = (lane >> 4) * 8;
        #pragma unroll
        for (int ks = 0; ks < 12; ++ks){
            uint32_t aH = smem_u32(sH + row*ASTRIDE + ks*16 + coff);
            uint32_t aL = smem_u32(sL + row*ASTRIDE + ks*16 + coff);
            ldmx4(ah[ks], aH);
            ldmx4(al[ks], aL);
        }
    }

    const int rowg = blockIdx.x*128 + wid*16 + (lane >> 2);
    const int cloc = (lane & 3) * 2;

    for (int nt = 0; nt < ntCount; ++nt){
        const uint4* bp = g_wfrag + (size_t)(ntStart + nt)*384 + lane;
        float c0[4] = {0,0,0,0}, c1[4] = {0,0,0,0}, c2[4] = {0,0,0,0};
        #pragma unroll
        for (int ks = 0; ks < 12; ++ks){
            uint4 bv = bp[ks*32];
            mma16816(c0, ah[ks], bv.x, bv.y);
            mma16816(c1, al[ks], bv.x, bv.y);
            mma16816(c2, ah[ks], bv.z, bv.w);
        }
        int cb = nt*8 + cloc;
        float b0 = g_bias[biasOff + cb], b1 = g_bias[biasOff + cb + 1];
        float2 o0, o1;
        o0.x = c0[0] + c1[0] + c2[0] + b0;
        o0.y = c0[1] + c1[1] + c2[1] + b1;
        o1.x = c0[2] + c1[2] + c2[2] + b0;
        o1.y = c0[3] + c1[3] + c2[3] + b1;
        *(float2*)(Out + (size_t)rowg     * outStride + cb) = o0;
        *(float2*)(Out + (size_t)(rowg+8) * outStride + cb) = o1;
    }
}

// =====================================================================
// Attention: one CTA per (window, head). 64 threads, f32x2 inner loops.
// Thread i (<49) owns query row i.
// =====================================================================
#define SCP 51

__global__ __launch_bounds__(64, 9)
void attn_kernel(const float* __restrict__ table,
                 const float* __restrict__ qkv,
                 float* __restrict__ att)
{
    __shared__ float sK[NTOK*32];
    __shared__ float sV[NTOK*32];
    __shared__ float sSC[NTOK*SCP];
    __shared__ float sB[169];
    __shared__ int   PIX[NTOK];
    __shared__ int   CNT[NTOK];

    const int tid = threadIdx.x;
    const int win = blockIdx.x;
    const int h   = blockIdx.y;
    const int b   = win >> 6, wi = win & 63;
    const int wh  = wi >> 3,  ww = wi & 7;
    const int mh  = b >> 3,   mw = b & 7;   // mask window = BATCH index (reference quirk)

    if (tid < NTOK){
        int th = tid / 7, tw = tid - th*7;
        int hh = wh*7 + th + 3; if (hh >= RES) hh -= RES;
        int wc = ww*7 + tw + 3; if (wc >= RES) wc -= RES;
        PIX[tid] = (b*RES + hh)*RES + wc;
        int mhs = mh*7 + th, mws = mw*7 + tw;
        int rh = (mhs < 49) ? 0 : ((mhs < 53) ? 1 : 2);
        int rw = (mws < 49) ? 0 : ((mws < 53) ? 1 : 2);
        CNT[tid] = rh*3 + rw;
    }
    for (int t = tid; t < 169; t += 64) sB[t] = __ldg(table + t*HEADS + h);
    __syncthreads();

    // gather K, V for this head (49 x 32 floats each)
    for (int f = tid; f < NTOK*8; f += 64){
        int t  = f >> 3;
        int c4 = (f & 7) * 4;
        const float* base = qkv + (size_t)PIX[t]*QKVC + h*32;
        *(float4*)(sK + t*32 + c4) = *(const float4*)(base + 192 + c4);
        *(float4*)(sV + t*32 + c4) = *(const float4*)(base + 384 + c4);
    }
    __syncthreads();

    if (tid < NTOK){
        const int i  = tid;
        const int ih = i / 7, iw = i - ih*7;
        const int ci = CNT[i];
        const float scale = 0.17677669529663687f;

        // Q row (32 floats) -> 16 packed f32x2 regs
        uint64_t q2[16];
        {
            const float4* qp = (const float4*)(qkv + (size_t)PIX[i]*QKVC + h*32);
            #pragma unroll
            for (int d = 0; d < 8; ++d){
                float4 v = qp[d];
                q2[d*2+0] = pack_x2(v.x, v.y);
                q2[d*2+1] = pack_x2(v.z, v.w);
            }
        }

        // ---- scores: packed dot + bias + mask ----
        float* srow = sSC + i*SCP;
        const uint32_t sKb = smem_u32(sK);
        int jh = 0, jw = 0;
        for (int j = 0; j < NTOK; ++j){
            uint32_t ka = sKb + j*128;
            uint64_t k2[16];
            #pragma unroll
            for (int d = 0; d < 8; ++d) lds_v2u64(k2[d*2], k2[d*2+1], ka + d*16);
            uint64_t a0 = mul_x2(q2[0], k2[0]);
            uint64_t a1 = mul_x2(q2[1], k2[1]);
            uint64_t a2 = mul_x2(q2[2], k2[2]);
            uint64_t a3 = mul_x2(q2[3], k2[3]);
            #pragma unroll
            for (int d = 4; d < 16; d += 4){
                a0 = fma_x2(q2[d+0], k2[d+0], a0);
                a1 = fma_x2(q2[d+1], k2[d+1], a1);
                a2 = fma_x2(q2[d+2], k2[d+2], a2);
                a3 = fma_x2(q2[d+3], k2[d+3], a3);
            }
            uint64_t s01 = add_x2(a0, a1);
            uint64_t s23 = add_x2(a2, a3);
            uint64_t s   = add_x2(s01, s23);
            float lo, hi; unpack_x2(lo, hi, s);
            float bias = sB[(ih - jh + 6)*13 + (iw - jw + 6)];
            float mv = (ci == CNT[j]) ? 0.f : -1000.f;
            srow[j] = fmaf(lo + hi, scale, bias + mv);
            if (++jw == 7){ jw = 0; ++jh; }
        }

        // ---- softmax ----
        float mx = -1e30f;
        #pragma unroll 7
        for (int j = 0; j < NTOK; ++j) mx = fmaxf(mx, srow[j]);
        float sum = 0.f;
        #pragma unroll 7
        for (int j = 0; j < NTOK; ++j){ float e = __expf(srow[j] - mx); srow[j] = e; sum += e; }
        float inv = __fdividef(1.f, sum);

        // ---- O = P @ V, packed accumulators ----
        uint64_t acc[16];
        const uint32_t sVb = smem_u32(sV);
        {
            // j = 0 initializes
            float p0 = srow[0];
            uint64_t pd = pack_x2(p0, p0);
            uint64_t v2[16];
            #pragma unroll
            for (int d = 0; d < 8; ++d) lds_v2u64(v2[d*2], v2[d*2+1], sVb + d*16);
            #pragma unroll
            for (int d = 0; d < 16; ++d) acc[d] = mul_x2(pd, v2[d]);
        }
        for (int j = 1; j < NTOK; ++j){
            float p = srow[j];
            uint64_t pd = pack_x2(p, p);
            uint32_t va = sVb + j*128;
            uint64_t v2[16];
            #pragma unroll
            for (int d = 0; d < 8; ++d) lds_v2u64(v2[d*2], v2[d*2+1], va + d*16);
            #pragma unroll
            for (int d = 0; d < 16; ++d) acc[d] = fma_x2(pd, v2[d], acc[d]);
        }
        uint64_t inv2 = pack_x2(inv, inv);
        float* ob = att + (size_t)PIX[i]*DIMS + h*32;
        #pragma unroll
        for (int d = 0; d < 4; ++d){
            float4 o;
            uint64_t r0 = mul_x2(acc[d*4+0], inv2);
            uint64_t r1 = mul_x2(acc[d*4+1], inv2);
            unpack_x2(o.x, o.y, r0);
            unpack_x2(o.z, o.w, r1);
            *(float4*)(ob + d*8) = o;
            float4 o2;
            uint64_t r2 = mul_x2(acc[d*4+2], inv2);
            uint64_t r3 = mul_x2(acc[d*4+3], inv2);
            unpack_x2(o2.x, o2.y, r2);
            unpack_x2(o2.z, o2.w, r3);
            *(float4*)(ob + d*8 + 4) = o2;
        }
    }
}

// =====================================================================
extern "C" void kernel_launch(void* const* d_in, const int* in_sizes, int n_in,
                              void* d_out, int out_size)
{
    const float* x     = (const float*)d_in[0];
    const float* table = (const float*)d_in[1];
    const float* wq    = (const float*)d_in[2];
    const float* bq    = (const float*)d_in[3];
    const float* wk    = (const float*)d_in[4];
    const float* bk    = (const float*)d_in[5];
    const float* wv    = (const float*)d_in[6];
    const float* bv    = (const float*)d_in[7];
    const float* wo    = (const float*)d_in[8];
    const float* bo    = (const float*)d_in[9];
    float* out = (float*)d_out;

    void* qkvp = nullptr; void* attp = nullptr;
    cudaGetSymbolAddress(&qkvp, g_qkv);
    cudaGetSymbolAddress(&attp, g_att);

    cudaFuncSetAttribute(mma_gemm, cudaFuncAttributeMaxDynamicSharedMemorySize, GEMM_SMEM);

    // 0) weight fragment prep
    wprep_kernel<<<144, 256>>>(wq, wk, wv, wo, bq, bk, bv, bo);
    // 1) QKV projection
    mma_gemm<<<NPIX/128, 256, GEMM_SMEM>>>(x, (float*)qkvp, QKVC, 0, 72, 0);
    // 2) windowed attention, one CTA per (window, head)
    dim3 ag(4096, 6);
    attn_kernel<<<ag, 64>>>(table, (const float*)qkvp, (float*)attp);
    // 3) output projection
    mma_gemm<<<NPIX/128, 256, GEMM_SMEM>>>((const float*)attp, out, DIMS, 72, 24, 576);
}